// round 1
// baseline (speedup 1.0000x reference)
#include <cuda_runtime.h>
#include <cuda_bf16.h>
#include <math.h>

// ---------------------------------------------------------------------------
// TransformerBlock: S=2048, d=1024, H=16, dk=64, dff=4096, B=1
// Output = concat(out [2048*1024], attn_weights [16*2048*2048]) fp32
// ---------------------------------------------------------------------------

#define S 2048
#define D 1024
#define H 16
#define DK 64
#define DFF 4096
#define OUT_ELEMS (S * D)

// Scratch (device globals: allocation-free per harness rules)
__device__ float g_nx[S * D];
__device__ float g_h[S * D];
__device__ float g_q[S * D];
__device__ float g_k[S * D];
__device__ float g_v[S * D];
__device__ float g_ctx[S * D];
__device__ float g_tmp[S * D];
__device__ float g_part1[S * D];
__device__ float g_n2[S * D];
__device__ float g_ff[S * DFF];

// ---------------------------------------------------------------------------
// LayerNorm: y = g*(x-mean)/(std+eps)+b, std = sqrt(biased var). One block/row.
// ---------------------------------------------------------------------------
__global__ __launch_bounds__(256) void ln_kernel(
    const float* __restrict__ x, const float* __restrict__ g,
    const float* __restrict__ b, float* __restrict__ y)
{
    const int row = blockIdx.x;
    const float* xr = x + (size_t)row * D;
    float vals[4];
    float s = 0.f, s2 = 0.f;
#pragma unroll
    for (int t = 0; t < 4; t++) {
        float u = xr[threadIdx.x + t * 256];
        vals[t] = u;
        s += u;
        s2 += u * u;
    }
    // block reduce (sum, sumsq)
    __shared__ float sm1[8], sm2[8];
#pragma unroll
    for (int o = 16; o; o >>= 1) {
        s  += __shfl_xor_sync(0xffffffffu, s,  o);
        s2 += __shfl_xor_sync(0xffffffffu, s2, o);
    }
    int wid = threadIdx.x >> 5;
    if ((threadIdx.x & 31) == 0) { sm1[wid] = s; sm2[wid] = s2; }
    __syncthreads();
    if (threadIdx.x < 8) {
        float a = sm1[threadIdx.x], c = sm2[threadIdx.x];
#pragma unroll
        for (int o = 4; o; o >>= 1) {
            a += __shfl_xor_sync(0xffu, a, o);
            c += __shfl_xor_sync(0xffu, c, o);
        }
        if (threadIdx.x == 0) { sm1[0] = a; sm2[0] = c; }
    }
    __syncthreads();
    float mean = sm1[0] * (1.f / D);
    float var = fmaxf(sm2[0] * (1.f / D) - mean * mean, 0.f);
    float inv = 1.f / (sqrtf(var) + 1e-6f);
#pragma unroll
    for (int t = 0; t < 4; t++) {
        int c = threadIdx.x + t * 256;
        y[(size_t)row * D + c] = g[c] * ((vals[t] - mean) * inv) + b[c];
    }
}

// ---------------------------------------------------------------------------
// SGEMM: C[M,N] = A[M,K] @ B[K,N] + bias[N] (+epilogue)
// 128x128 block tile, BK=8, 256 threads, 8x8/thread in 4+4 split layout.
// epi: 0 = bias, 1 = bias+relu, 2 = bias + res[M,N]
// Requires M%128==0, N%128==0, K%8==0.
// ---------------------------------------------------------------------------
__global__ __launch_bounds__(256) void sgemm128(
    const float* __restrict__ A, const float* __restrict__ B,
    const float* __restrict__ bias, const float* __restrict__ res,
    float* __restrict__ C, int M, int N, int K, int epi)
{
    __shared__ __align__(16) float As[8][128];
    __shared__ __align__(16) float Bs[8][128];
    const int tid = threadIdx.x;
    const int bx = blockIdx.x, by = blockIdx.y;
    const int tc = tid & 15;   // 0..15
    const int tr = tid >> 4;   // 0..15

    float acc[8][8];
#pragma unroll
    for (int i = 0; i < 8; i++)
#pragma unroll
        for (int j = 0; j < 8; j++) acc[i][j] = 0.f;

    // global load indices
    const int aRow  = tid >> 1;           // 0..127
    const int aCol4 = (tid & 1) * 4;      // 0 or 4
    const int bRow  = tid >> 5;           // 0..7
    const int bCol  = (tid & 31) * 4;     // 0..124

    const float* Aptr = A + (size_t)(by * 128) * K;
    const float* Bptr = B + bx * 128;

    for (int k0 = 0; k0 < K; k0 += 8) {
        float4 av = *reinterpret_cast<const float4*>(Aptr + (size_t)aRow * K + k0 + aCol4);
        As[aCol4 + 0][aRow] = av.x;
        As[aCol4 + 1][aRow] = av.y;
        As[aCol4 + 2][aRow] = av.z;
        As[aCol4 + 3][aRow] = av.w;
        *reinterpret_cast<float4*>(&Bs[bRow][bCol]) =
            *reinterpret_cast<const float4*>(Bptr + (size_t)(k0 + bRow) * N + bCol);
        __syncthreads();
#pragma unroll
        for (int k = 0; k < 8; k++) {
            float4 a0 = *reinterpret_cast<const float4*>(&As[k][tr * 4]);
            float4 a1 = *reinterpret_cast<const float4*>(&As[k][64 + tr * 4]);
            float4 b0 = *reinterpret_cast<const float4*>(&Bs[k][tc * 4]);
            float4 b1 = *reinterpret_cast<const float4*>(&Bs[k][64 + tc * 4]);
            float a[8] = {a0.x, a0.y, a0.z, a0.w, a1.x, a1.y, a1.z, a1.w};
            float b[8] = {b0.x, b0.y, b0.z, b0.w, b1.x, b1.y, b1.z, b1.w};
#pragma unroll
            for (int i = 0; i < 8; i++)
#pragma unroll
                for (int j = 0; j < 8; j++)
                    acc[i][j] = fmaf(a[i], b[j], acc[i][j]);
        }
        __syncthreads();
    }

    const int rBase = by * 128 + tr * 4;
    const int cBase = bx * 128 + tc * 4;
#pragma unroll
    for (int i = 0; i < 8; i++) {
        int r = rBase + (i & 3) + (i >> 2) * 64;
#pragma unroll
        for (int j = 0; j < 8; j++) {
            int c = cBase + (j & 3) + (j >> 2) * 64;
            float v = acc[i][j] + bias[c];
            if (epi == 1) v = fmaxf(v, 0.f);
            else if (epi == 2) v += res[(size_t)r * N + c];
            C[(size_t)r * N + c] = v;
        }
    }
}

// ---------------------------------------------------------------------------
// Scores: raw = (Q_h @ K_h^T) / 8 for lower-triangular 64x64 tiles only.
// grid: (ktile=32, qtile=32, head=16), 256 threads, 4x4 per thread.
// ---------------------------------------------------------------------------
__global__ __launch_bounds__(256) void scores_kernel(
    const float* __restrict__ q, const float* __restrict__ k,
    float* __restrict__ attn)
{
    const int kt = blockIdx.x, qt = blockIdx.y, h = blockIdx.z;
    if (kt > qt) return;
    __shared__ float Qs[64][65];
    __shared__ float Ks[64][65];
    const int tid = threadIdx.x;
    for (int i = tid; i < 64 * 64; i += 256) {
        int r = i >> 6, c = i & 63;
        Qs[r][c] = q[(size_t)(qt * 64 + r) * D + h * 64 + c];
        Ks[r][c] = k[(size_t)(kt * 64 + r) * D + h * 64 + c];
    }
    __syncthreads();
    const int tc = tid & 15, tr = tid >> 4;
    float acc[4][4];
#pragma unroll
    for (int i = 0; i < 4; i++)
#pragma unroll
        for (int j = 0; j < 4; j++) acc[i][j] = 0.f;

    for (int kk = 0; kk < 64; kk++) {
        float a[4], b[4];
#pragma unroll
        for (int i = 0; i < 4; i++) a[i] = Qs[tr * 4 + i][kk];
#pragma unroll
        for (int j = 0; j < 4; j++) b[j] = Ks[tc * 4 + j][kk];
#pragma unroll
        for (int i = 0; i < 4; i++)
#pragma unroll
            for (int j = 0; j < 4; j++) acc[i][j] = fmaf(a[i], b[j], acc[i][j]);
    }
    float* out = attn + ((size_t)(h * S + qt * 64)) * S + kt * 64;
#pragma unroll
    for (int i = 0; i < 4; i++)
#pragma unroll
        for (int j = 0; j < 4; j++)
            out[(size_t)(tr * 4 + i) * S + tc * 4 + j] = acc[i][j] * 0.125f;
}

// ---------------------------------------------------------------------------
// Causal softmax in-place over attn rows. Reads only j<=i (rest is garbage),
// writes full row of 2048 (zeros beyond diagonal). grid: (row=2048, head=16).
// ---------------------------------------------------------------------------
__global__ __launch_bounds__(256) void softmax_kernel(float* __restrict__ attn)
{
    const int i = blockIdx.x, h = blockIdx.y;
    float* row = attn + ((size_t)h * S + i) * S;
    const int len = i + 1;
    const int tid = threadIdx.x;
    float v[8];
    float mx = -INFINITY;
#pragma unroll
    for (int t = 0; t < 8; t++) {
        int j = tid + t * 256;
        v[t] = (j < len) ? row[j] : -INFINITY;
        mx = fmaxf(mx, v[t]);
    }
    __shared__ float sm[8];
#pragma unroll
    for (int o = 16; o; o >>= 1) mx = fmaxf(mx, __shfl_xor_sync(0xffffffffu, mx, o));
    int wid = tid >> 5;
    if ((tid & 31) == 0) sm[wid] = mx;
    __syncthreads();
    if (tid < 8) {
        float w = sm[tid];
#pragma unroll
        for (int o = 4; o; o >>= 1) w = fmaxf(w, __shfl_xor_sync(0xffu, w, o));
        if (tid == 0) sm[0] = w;
    }
    __syncthreads();
    const float rmax = sm[0];
    __syncthreads();

    float sum = 0.f;
#pragma unroll
    for (int t = 0; t < 8; t++) {
        int j = tid + t * 256;
        float e = (j < len) ? __expf(v[t] - rmax) : 0.f;
        v[t] = e;
        sum += e;
    }
#pragma unroll
    for (int o = 16; o; o >>= 1) sum += __shfl_xor_sync(0xffffffffu, sum, o);
    if ((tid & 31) == 0) sm[wid] = sum;
    __syncthreads();
    if (tid < 8) {
        float w = sm[tid];
#pragma unroll
        for (int o = 4; o; o >>= 1) w += __shfl_xor_sync(0xffu, w, o);
        if (tid == 0) sm[0] = w;
    }
    __syncthreads();
    const float inv = 1.f / sm[0];
#pragma unroll
    for (int t = 0; t < 8; t++) {
        int j = tid + t * 256;
        row[j] = v[t] * inv;
    }
}

// ---------------------------------------------------------------------------
// ctx = attn_h @ V_h, skipping zero tiles (kt > qt). grid: (qtile=32, head=16).
// ---------------------------------------------------------------------------
__global__ __launch_bounds__(256) void ctx_kernel(
    const float* __restrict__ attn, const float* __restrict__ v,
    float* __restrict__ ctx)
{
    const int qt = blockIdx.x, h = blockIdx.y;
    __shared__ float Asm[64][65];
    __shared__ float Vs[64][65];
    const int tid = threadIdx.x;
    const int tc = tid & 15, tr = tid >> 4;
    float acc[4][4];
#pragma unroll
    for (int i = 0; i < 4; i++)
#pragma unroll
        for (int j = 0; j < 4; j++) acc[i][j] = 0.f;

    for (int kt = 0; kt <= qt; kt++) {
        for (int i = tid; i < 64 * 64; i += 256) {
            int r = i >> 6, c = i & 63;
            Asm[r][c] = attn[((size_t)(h * S + qt * 64 + r)) * S + kt * 64 + c];
            Vs[r][c] = v[(size_t)(kt * 64 + r) * D + h * 64 + c];
        }
        __syncthreads();
#pragma unroll 8
        for (int kk = 0; kk < 64; kk++) {
            float a[4], b[4];
#pragma unroll
            for (int i = 0; i < 4; i++) a[i] = Asm[tr * 4 + i][kk];
#pragma unroll
            for (int j = 0; j < 4; j++) b[j] = Vs[kk][tc * 4 + j];
#pragma unroll
            for (int i = 0; i < 4; i++)
#pragma unroll
                for (int j = 0; j < 4; j++) acc[i][j] = fmaf(a[i], b[j], acc[i][j]);
        }
        __syncthreads();
    }
#pragma unroll
    for (int i = 0; i < 4; i++)
#pragma unroll
        for (int j = 0; j < 4; j++)
            ctx[(size_t)(qt * 64 + tr * 4 + i) * D + h * 64 + tc * 4 + j] = acc[i][j];
}

// ---------------------------------------------------------------------------
// Host launcher
// ---------------------------------------------------------------------------
extern "C" void kernel_launch(void* const* d_in, const int* in_sizes, int n_in,
                              void* d_out, int out_size)
{
    (void)in_sizes; (void)n_in; (void)out_size;
    const float* x     = (const float*)d_in[0];
    const float* g1    = (const float*)d_in[1];
    const float* beta1 = (const float*)d_in[2];
    const float* W_in  = (const float*)d_in[3];
    const float* b_in  = (const float*)d_in[4];
    const float* Wq    = (const float*)d_in[5];
    const float* bq    = (const float*)d_in[6];
    const float* Wk    = (const float*)d_in[7];
    const float* bk    = (const float*)d_in[8];
    const float* Wv    = (const float*)d_in[9];
    const float* bv    = (const float*)d_in[10];
    const float* Wo    = (const float*)d_in[11];
    const float* bo    = (const float*)d_in[12];
    const float* W2    = (const float*)d_in[13];
    const float* b2    = (const float*)d_in[14];
    const float* g2    = (const float*)d_in[15];
    const float* beta2 = (const float*)d_in[16];
    const float* Wf1   = (const float*)d_in[17];
    const float* bf1   = (const float*)d_in[18];
    const float* Wf2   = (const float*)d_in[19];
    const float* bf2   = (const float*)d_in[20];

    float* out  = (float*)d_out;
    float* attn = out + (size_t)OUT_ELEMS;   // [16,2048,2048]

    float *nx, *h, *q, *k, *v, *ctx, *tmp, *part1, *n2, *ff;
    cudaGetSymbolAddress((void**)&nx,    g_nx);
    cudaGetSymbolAddress((void**)&h,     g_h);
    cudaGetSymbolAddress((void**)&q,     g_q);
    cudaGetSymbolAddress((void**)&k,     g_k);
    cudaGetSymbolAddress((void**)&v,     g_v);
    cudaGetSymbolAddress((void**)&ctx,   g_ctx);
    cudaGetSymbolAddress((void**)&tmp,   g_tmp);
    cudaGetSymbolAddress((void**)&part1, g_part1);
    cudaGetSymbolAddress((void**)&n2,    g_n2);
    cudaGetSymbolAddress((void**)&ff,    g_ff);

    // 1) LN1
    ln_kernel<<<S, 256>>>(x, g1, beta1, nx);
    // 2) h = nx @ W_in + b_in
    sgemm128<<<dim3(D / 128, S / 128), 256>>>(nx, W_in, b_in, nullptr, h, S, D, D, 0);
    // 3) q/k/v
    sgemm128<<<dim3(D / 128, S / 128), 256>>>(h, Wq, bq, nullptr, q, S, D, D, 0);
    sgemm128<<<dim3(D / 128, S / 128), 256>>>(h, Wk, bk, nullptr, k, S, D, D, 0);
    sgemm128<<<dim3(D / 128, S / 128), 256>>>(h, Wv, bv, nullptr, v, S, D, D, 0);
    // 4) causal scores into attn region (scratch = final output buffer)
    scores_kernel<<<dim3(32, 32, H), 256>>>(q, k, attn);
    // 5) in-place causal softmax -> final attn_weights
    softmax_kernel<<<dim3(S, H), 256>>>(attn);
    // 6) ctx = attn @ v (per head)
    ctx_kernel<<<dim3(32, H), 256>>>(attn, v, ctx);
    // 7) mha_out = ctx @ Wo + bo
    sgemm128<<<dim3(D / 128, S / 128), 256>>>(ctx, Wo, bo, nullptr, tmp, S, D, D, 0);
    // 8) part1 = x + (mha_out @ W2 + b2)
    sgemm128<<<dim3(D / 128, S / 128), 256>>>(tmp, W2, b2, x, part1, S, D, D, 2);
    // 9) LN2
    ln_kernel<<<S, 256>>>(part1, g2, beta2, n2);
    // 10) ff hidden = relu(n2 @ Wf1 + bf1)
    sgemm128<<<dim3(DFF / 128, S / 128), 256>>>(n2, Wf1, bf1, nullptr, ff, S, DFF, D, 1);
    // 11) out = n2 + (ff @ Wf2 + bf2)
    sgemm128<<<dim3(D / 128, S / 128), 256>>>(ff, Wf2, bf2, n2, out, S, D, DFF, 2);
}

// round 4
// speedup vs baseline: 1.9877x; 1.9877x over previous
#include <cuda_runtime.h>
#include <cuda_bf16.h>
#include <math.h>
#include <stdint.h>

// ---------------------------------------------------------------------------
// TransformerBlock: S=2048, d=1024, H=16, dk=64, dff=4096, B=1
// Output = concat(out [2048*1024], attn_weights [16*2048*2048]) fp32
// Dense GEMMs on tensor cores (mma.sync bf16) with split-fp32 compensation:
//   A = Ah + Al (bf16 hi/lo), C = Ah*Bh + Ah*Bl + Al*Bh  (fp32 accum)
// ---------------------------------------------------------------------------

#define S 2048
#define D 1024
#define H 16
#define DFF 4096
#define OUT_ELEMS (S * D)

// fp32 scratch
__device__ float g_q[S * D];
__device__ float g_k[S * D];
__device__ float g_v[S * D];
__device__ float g_part1[S * D];
__device__ float g_n2[S * D];
// bf16 hi/lo split activations
__device__ __nv_bfloat16 g_nx_h[S * D],  g_nx_l[S * D];
__device__ __nv_bfloat16 g_h_h[S * D],   g_h_l[S * D];
__device__ __nv_bfloat16 g_ctx_h[S * D], g_ctx_l[S * D];
__device__ __nv_bfloat16 g_tmp_h[S * D], g_tmp_l[S * D];
__device__ __nv_bfloat16 g_n2_h[S * D],  g_n2_l[S * D];
__device__ __nv_bfloat16 g_ff_h[S * DFF], g_ff_l[S * DFF];
// bf16 hi/lo split weights
__device__ __nv_bfloat16 g_Win_h[D * D], g_Win_l[D * D];
__device__ __nv_bfloat16 g_Wq_h[D * D],  g_Wq_l[D * D];
__device__ __nv_bfloat16 g_Wk_h[D * D],  g_Wk_l[D * D];
__device__ __nv_bfloat16 g_Wv_h[D * D],  g_Wv_l[D * D];
__device__ __nv_bfloat16 g_Wo_h[D * D],  g_Wo_l[D * D];
__device__ __nv_bfloat16 g_W2_h[D * D],  g_W2_l[D * D];
__device__ __nv_bfloat16 g_Wf1_h[D * DFF], g_Wf1_l[D * DFF];
__device__ __nv_bfloat16 g_Wf2_h[DFF * D], g_Wf2_l[DFF * D];

// ---------------------------------------------------------------------------
// helpers
// ---------------------------------------------------------------------------
__device__ __forceinline__ void split2(float v, __nv_bfloat16& h, __nv_bfloat16& l) {
    h = __float2bfloat16(v);
    l = __float2bfloat16(v - __bfloat162float(h));
}

__device__ __forceinline__ uint32_t smem_u32(const void* p) {
    return (uint32_t)__cvta_generic_to_shared(p);
}

__device__ __forceinline__ void cp16(void* smem, const void* g) {
    uint32_t s = smem_u32(smem);
    asm volatile("cp.async.cg.shared.global [%0], [%1], 16;\n" :: "r"(s), "l"(g));
}

__device__ __forceinline__ void ldm_x4(uint32_t* r, uint32_t addr) {
    asm volatile("ldmatrix.sync.aligned.m8n8.x4.shared.b16 {%0,%1,%2,%3}, [%4];\n"
                 : "=r"(r[0]), "=r"(r[1]), "=r"(r[2]), "=r"(r[3]) : "r"(addr));
}

__device__ __forceinline__ void ldm_x4_trans(uint32_t* r, uint32_t addr) {
    asm volatile("ldmatrix.sync.aligned.m8n8.x4.trans.shared.b16 {%0,%1,%2,%3}, [%4];\n"
                 : "=r"(r[0]), "=r"(r[1]), "=r"(r[2]), "=r"(r[3]) : "r"(addr));
}

__device__ __forceinline__ void mma16816(float* c, const uint32_t* a, const uint32_t* b) {
    asm volatile(
        "mma.sync.aligned.m16n8k16.row.col.f32.bf16.bf16.f32 "
        "{%0,%1,%2,%3}, {%4,%5,%6,%7}, {%8,%9}, {%0,%1,%2,%3};\n"
        : "+f"(c[0]), "+f"(c[1]), "+f"(c[2]), "+f"(c[3])
        : "r"(a[0]), "r"(a[1]), "r"(a[2]), "r"(a[3]), "r"(b[0]), "r"(b[1]));
}

// ---------------------------------------------------------------------------
// split_kernel: fp32 -> bf16 hi/lo
// ---------------------------------------------------------------------------
__global__ __launch_bounds__(256) void split_kernel(
    const float* __restrict__ s, __nv_bfloat16* __restrict__ h,
    __nv_bfloat16* __restrict__ l)
{
    int i = blockIdx.x * 256 + threadIdx.x;
    float v = s[i];
    __nv_bfloat16 hi = __float2bfloat16(v);
    h[i] = hi;
    l[i] = __float2bfloat16(v - __bfloat162float(hi));
}

// ---------------------------------------------------------------------------
// LayerNorm: y = g*(x-mean)/(std+eps)+b, std = sqrt(biased var). One block/row.
// Writes bf16 hi/lo always, fp32 optionally.
// ---------------------------------------------------------------------------
__global__ __launch_bounds__(256) void ln_kernel(
    const float* __restrict__ x, const float* __restrict__ g,
    const float* __restrict__ b, float* __restrict__ yf,
    __nv_bfloat16* __restrict__ yh, __nv_bfloat16* __restrict__ yl)
{
    const int row = blockIdx.x;
    const float* xr = x + (size_t)row * D;
    float vals[4];
    float s = 0.f, s2 = 0.f;
#pragma unroll
    for (int t = 0; t < 4; t++) {
        float u = xr[threadIdx.x + t * 256];
        vals[t] = u;
        s += u;
        s2 += u * u;
    }
    __shared__ float sm1[8], sm2[8];
#pragma unroll
    for (int o = 16; o; o >>= 1) {
        s  += __shfl_xor_sync(0xffffffffu, s,  o);
        s2 += __shfl_xor_sync(0xffffffffu, s2, o);
    }
    int wid = threadIdx.x >> 5;
    if ((threadIdx.x & 31) == 0) { sm1[wid] = s; sm2[wid] = s2; }
    __syncthreads();
    if (threadIdx.x < 8) {
        float a = sm1[threadIdx.x], c = sm2[threadIdx.x];
#pragma unroll
        for (int o = 4; o; o >>= 1) {
            a += __shfl_xor_sync(0xffu, a, o);
            c += __shfl_xor_sync(0xffu, c, o);
        }
        if (threadIdx.x == 0) { sm1[0] = a; sm2[0] = c; }
    }
    __syncthreads();
    float mean = sm1[0] * (1.f / D);
    float var = fmaxf(sm2[0] * (1.f / D) - mean * mean, 0.f);
    float inv = 1.f / (sqrtf(var) + 1e-6f);
#pragma unroll
    for (int t = 0; t < 4; t++) {
        int c = threadIdx.x + t * 256;
        float v = g[c] * ((vals[t] - mean) * inv) + b[c];
        size_t idx = (size_t)row * D + c;
        if (yf) yf[idx] = v;
        __nv_bfloat16 hi, lo;
        split2(v, hi, lo);
        yh[idx] = hi;
        yl[idx] = lo;
    }
}

// ---------------------------------------------------------------------------
// Tensor-core GEMM: C[M,N] = (Ah+Al)[M,K] @ (Bh+Bl)[K,N] + bias (+epilogue)
// BM=128, BN=64, BK=16, 256 threads (8 warps 4x2), warp tile 32x32.
// cp.async double-buffered. relu flag; res: fp32 residual (nullable);
// Cf: fp32 out (nullable); Ch/Cl: bf16 split out (nullable).
// ---------------------------------------------------------------------------
__global__ __launch_bounds__(256) void gemm_mma(
    const __nv_bfloat16* __restrict__ Ah, const __nv_bfloat16* __restrict__ Al,
    const __nv_bfloat16* __restrict__ Bh, const __nv_bfloat16* __restrict__ Bl,
    const float* __restrict__ bias, const float* __restrict__ res,
    float* __restrict__ Cf, __nv_bfloat16* __restrict__ Ch,
    __nv_bfloat16* __restrict__ Cl, int N, int K, int relu)
{
    __shared__ __align__(16) __nv_bfloat16 As[2][2][128][24];  // [stage][hi/lo][m][k] pad 24
    __shared__ __align__(16) __nv_bfloat16 Bs[2][2][16][72];   // [stage][hi/lo][k][n] pad 72

    const int tid = threadIdx.x;
    const int m0 = blockIdx.y * 128, n0 = blockIdx.x * 64;
    const int warp = tid >> 5, lane = tid & 31;
    const int wm = warp >> 1, wn = warp & 1;   // 4x2 warps, warp tile 32x32

    float acc[2][4][4] = {};

    auto issue = [&](int stg, int it) {
        const int k0 = it * 16;
        const int ar = tid >> 1, ac = (tid & 1) * 8;
        cp16(&As[stg][0][ar][ac], Ah + (size_t)(m0 + ar) * K + k0 + ac);
        cp16(&As[stg][1][ar][ac], Al + (size_t)(m0 + ar) * K + k0 + ac);
        if (tid < 128) {
            const int br = tid >> 3, bc = (tid & 7) * 8;
            cp16(&Bs[stg][0][br][bc], Bh + (size_t)(k0 + br) * N + n0 + bc);
        } else {
            const int t2 = tid - 128, br = t2 >> 3, bc = (t2 & 7) * 8;
            cp16(&Bs[stg][1][br][bc], Bl + (size_t)(k0 + br) * N + n0 + bc);
        }
        asm volatile("cp.async.commit_group;\n" ::: "memory");
    };

    const int nIter = K >> 4;
    issue(0, 0);
    for (int it = 0; it < nIter; ++it) {
        const int s = it & 1;
        if (it + 1 < nIter) {
            issue(s ^ 1, it + 1);
            asm volatile("cp.async.wait_group 1;\n" ::: "memory");
        } else {
            asm volatile("cp.async.wait_group 0;\n" ::: "memory");
        }
        __syncthreads();

        uint32_t a[2][2][4];  // [hi/lo][mtile][4]
        uint32_t b[2][4][2];  // [hi/lo][ntile][2]
#pragma unroll
        for (int hl = 0; hl < 2; hl++) {
#pragma unroll
            for (int mt = 0; mt < 2; mt++) {
                uint32_t addr = smem_u32(
                    &As[s][hl][wm * 32 + mt * 16 + (lane & 15)][(lane >> 4) * 8]);
                ldm_x4(a[hl][mt], addr);
            }
#pragma unroll
            for (int np = 0; np < 2; np++) {
                uint32_t r4[4];
                uint32_t addr = smem_u32(
                    &Bs[s][hl][lane & 15][wn * 32 + np * 16 + (lane >> 4) * 8]);
                ldm_x4_trans(r4, addr);
                b[hl][np * 2][0]     = r4[0];
                b[hl][np * 2][1]     = r4[1];
                b[hl][np * 2 + 1][0] = r4[2];
                b[hl][np * 2 + 1][1] = r4[3];
            }
        }
#pragma unroll
        for (int mt = 0; mt < 2; mt++)
#pragma unroll
            for (int nt = 0; nt < 4; nt++) {
                mma16816(acc[mt][nt], a[0][mt], b[0][nt]);  // hi*hi
                mma16816(acc[mt][nt], a[0][mt], b[1][nt]);  // hi*lo
                mma16816(acc[mt][nt], a[1][mt], b[0][nt]);  // lo*hi
            }
        __syncthreads();
    }

    // epilogue
#pragma unroll
    for (int mt = 0; mt < 2; mt++) {
#pragma unroll
        for (int nt = 0; nt < 4; nt++) {
            int r = m0 + wm * 32 + mt * 16 + (lane >> 2);
            int c = n0 + wn * 32 + nt * 8 + (lane & 3) * 2;
            float b0 = bias[c], b1 = bias[c + 1];
            float v0 = acc[mt][nt][0] + b0;
            float v1 = acc[mt][nt][1] + b1;
            float v2 = acc[mt][nt][2] + b0;
            float v3 = acc[mt][nt][3] + b1;
            if (relu) {
                v0 = fmaxf(v0, 0.f); v1 = fmaxf(v1, 0.f);
                v2 = fmaxf(v2, 0.f); v3 = fmaxf(v3, 0.f);
            }
            if (res) {
                v0 += res[(size_t)r * N + c];
                v1 += res[(size_t)r * N + c + 1];
                v2 += res[(size_t)(r + 8) * N + c];
                v3 += res[(size_t)(r + 8) * N + c + 1];
            }
            if (Cf) {
                float2 f01 = make_float2(v0, v1);
                float2 f23 = make_float2(v2, v3);
                *(float2*)&Cf[(size_t)r * N + c] = f01;
                *(float2*)&Cf[(size_t)(r + 8) * N + c] = f23;
            }
            if (Ch) {
                __nv_bfloat16 h0, l0, h1, l1, h2, l2, h3, l3;
                split2(v0, h0, l0); split2(v1, h1, l1);
                split2(v2, h2, l2); split2(v3, h3, l3);
                __nv_bfloat162 hv, lv;
                hv.x = h0; hv.y = h1; lv.x = l0; lv.y = l1;
                *(__nv_bfloat162*)&Ch[(size_t)r * N + c] = hv;
                *(__nv_bfloat162*)&Cl[(size_t)r * N + c] = lv;
                hv.x = h2; hv.y = h3; lv.x = l2; lv.y = l3;
                *(__nv_bfloat162*)&Ch[(size_t)(r + 8) * N + c] = hv;
                *(__nv_bfloat162*)&Cl[(size_t)(r + 8) * N + c] = lv;
            }
        }
    }
}

// ---------------------------------------------------------------------------
// Scores: raw = (Q_h @ K_h^T) / 8 for lower-triangular 64x64 tiles only.
// ---------------------------------------------------------------------------
__global__ __launch_bounds__(256) void scores_kernel(
    const float* __restrict__ q, const float* __restrict__ k,
    float* __restrict__ attn)
{
    const int kt = blockIdx.x, qt = blockIdx.y, h = blockIdx.z;
    if (kt > qt) return;
    __shared__ float Qs[64][65];
    __shared__ float Ks[64][65];
    const int tid = threadIdx.x;
    for (int i = tid; i < 64 * 64; i += 256) {
        int r = i >> 6, c = i & 63;
        Qs[r][c] = q[(size_t)(qt * 64 + r) * D + h * 64 + c];
        Ks[r][c] = k[(size_t)(kt * 64 + r) * D + h * 64 + c];
    }
    __syncthreads();
    const int tc = tid & 15, tr = tid >> 4;
    float acc[4][4] = {};
    for (int kk = 0; kk < 64; kk++) {
        float a[4], b[4];
#pragma unroll
        for (int i = 0; i < 4; i++) a[i] = Qs[tr * 4 + i][kk];
#pragma unroll
        for (int j = 0; j < 4; j++) b[j] = Ks[tc * 4 + j][kk];
#pragma unroll
        for (int i = 0; i < 4; i++)
#pragma unroll
            for (int j = 0; j < 4; j++) acc[i][j] = fmaf(a[i], b[j], acc[i][j]);
    }
    float* out = attn + ((size_t)(h * S + qt * 64)) * S + kt * 64;
#pragma unroll
    for (int i = 0; i < 4; i++)
#pragma unroll
        for (int j = 0; j < 4; j++)
            out[(size_t)(tr * 4 + i) * S + tc * 4 + j] = acc[i][j] * 0.125f;
}

// ---------------------------------------------------------------------------
// Causal softmax in-place. grid: (row=2048, head=16).
// ---------------------------------------------------------------------------
__global__ __launch_bounds__(256) void softmax_kernel(float* __restrict__ attn)
{
    const int i = blockIdx.x, h = blockIdx.y;
    float* row = attn + ((size_t)h * S + i) * S;
    const int len = i + 1;
    const int tid = threadIdx.x;
    float v[8];
    float mx = -INFINITY;
#pragma unroll
    for (int t = 0; t < 8; t++) {
        int j = tid + t * 256;
        v[t] = (j < len) ? row[j] : -INFINITY;
        mx = fmaxf(mx, v[t]);
    }
    __shared__ float sm[8];
#pragma unroll
    for (int o = 16; o; o >>= 1) mx = fmaxf(mx, __shfl_xor_sync(0xffffffffu, mx, o));
    int wid = tid >> 5;
    if ((tid & 31) == 0) sm[wid] = mx;
    __syncthreads();
    if (tid < 8) {
        float w = sm[tid];
#pragma unroll
        for (int o = 4; o; o >>= 1) w = fmaxf(w, __shfl_xor_sync(0xffu, w, o));
        if (tid == 0) sm[0] = w;
    }
    __syncthreads();
    const float rmax = sm[0];
    __syncthreads();

    float sum = 0.f;
#pragma unroll
    for (int t = 0; t < 8; t++) {
        int j = tid + t * 256;
        float e = (j < len) ? __expf(v[t] - rmax) : 0.f;
        v[t] = e;
        sum += e;
    }
#pragma unroll
    for (int o = 16; o; o >>= 1) sum += __shfl_xor_sync(0xffffffffu, sum, o);
    if ((tid & 31) == 0) sm[wid] = sum;
    __syncthreads();
    if (tid < 8) {
        float w = sm[tid];
#pragma unroll
        for (int o = 4; o; o >>= 1) w += __shfl_xor_sync(0xffu, w, o);
        if (tid == 0) sm[0] = w;
    }
    __syncthreads();
    const float inv = 1.f / sm[0];
#pragma unroll
    for (int t = 0; t < 8; t++) {
        int j = tid + t * 256;
        row[j] = v[t] * inv;
    }
}

// ---------------------------------------------------------------------------
// ctx = attn_h @ V_h (skip zero tiles), writes bf16 hi/lo split.
// ---------------------------------------------------------------------------
__global__ __launch_bounds__(256) void ctx_kernel(
    const float* __restrict__ attn, const float* __restrict__ v,
    __nv_bfloat16* __restrict__ ch, __nv_bfloat16* __restrict__ cl)
{
    const int qt = blockIdx.x, h = blockIdx.y;
    __shared__ float Asm[64][65];
    __shared__ float Vs[64][65];
    const int tid = threadIdx.x;
    const int tc = tid & 15, tr = tid >> 4;
    float acc[4][4] = {};

    for (int kt = 0; kt <= qt; kt++) {
        for (int i = tid; i < 64 * 64; i += 256) {
            int r = i >> 6, c = i & 63;
            Asm[r][c] = attn[((size_t)(h * S + qt * 64 + r)) * S + kt * 64 + c];
            Vs[r][c] = v[(size_t)(kt * 64 + r) * D + h * 64 + c];
        }
        __syncthreads();
#pragma unroll 8
        for (int kk = 0; kk < 64; kk++) {
            float a[4], b[4];
#pragma unroll
            for (int i = 0; i < 4; i++) a[i] = Asm[tr * 4 + i][kk];
#pragma unroll
            for (int j = 0; j < 4; j++) b[j] = Vs[kk][tc * 4 + j];
#pragma unroll
            for (int i = 0; i < 4; i++)
#pragma unroll
                for (int j = 0; j < 4; j++) acc[i][j] = fmaf(a[i], b[j], acc[i][j]);
        }
        __syncthreads();
    }
#pragma unroll
    for (int i = 0; i < 4; i++)
#pragma unroll
        for (int j = 0; j < 4; j++) {
            size_t idx = (size_t)(qt * 64 + tr * 4 + i) * D + h * 64 + tc * 4 + j;
            __nv_bfloat16 hh, ll;
            split2(acc[i][j], hh, ll);
            ch[idx] = hh;
            cl[idx] = ll;
        }
}

// ---------------------------------------------------------------------------
// Host launcher
// ---------------------------------------------------------------------------
extern "C" void kernel_launch(void* const* d_in, const int* in_sizes, int n_in,
                              void* d_out, int out_size)
{
    (void)in_sizes; (void)n_in; (void)out_size;
    const float* x     = (const float*)d_in[0];
    const float* g1    = (const float*)d_in[1];
    const float* beta1 = (const float*)d_in[2];
    const float* W_in  = (const float*)d_in[3];
    const float* b_in  = (const float*)d_in[4];
    const float* Wq    = (const float*)d_in[5];
    const float* bq    = (const float*)d_in[6];
    const float* Wk    = (const float*)d_in[7];
    const float* bk    = (const float*)d_in[8];
    const float* Wv    = (const float*)d_in[9];
    const float* bv    = (const float*)d_in[10];
    const float* Wo    = (const float*)d_in[11];
    const float* bo    = (const float*)d_in[12];
    const float* W2    = (const float*)d_in[13];
    const float* b2    = (const float*)d_in[14];
    const float* g2    = (const float*)d_in[15];
    const float* beta2 = (const float*)d_in[16];
    const float* Wf1   = (const float*)d_in[17];
    const float* bf1   = (const float*)d_in[18];
    const float* Wf2   = (const float*)d_in[19];
    const float* bf2   = (const float*)d_in[20];

    float* out  = (float*)d_out;
    float* attn = out + (size_t)OUT_ELEMS;   // [16,2048,2048]

    float *q, *k, *v, *part1, *n2;
    cudaGetSymbolAddress((void**)&q,     g_q);
    cudaGetSymbolAddress((void**)&k,     g_k);
    cudaGetSymbolAddress((void**)&v,     g_v);
    cudaGetSymbolAddress((void**)&part1, g_part1);
    cudaGetSymbolAddress((void**)&n2,    g_n2);

    __nv_bfloat16 *nxh, *nxl, *hh, *hl, *ctxh, *ctxl, *tmph, *tmpl, *n2h, *n2l, *ffh, *ffl;
    cudaGetSymbolAddress((void**)&nxh,  g_nx_h);  cudaGetSymbolAddress((void**)&nxl,  g_nx_l);
    cudaGetSymbolAddress((void**)&hh,   g_h_h);   cudaGetSymbolAddress((void**)&hl,   g_h_l);
    cudaGetSymbolAddress((void**)&ctxh, g_ctx_h); cudaGetSymbolAddress((void**)&ctxl, g_ctx_l);
    cudaGetSymbolAddress((void**)&tmph, g_tmp_h); cudaGetSymbolAddress((void**)&tmpl, g_tmp_l);
    cudaGetSymbolAddress((void**)&n2h,  g_n2_h);  cudaGetSymbolAddress((void**)&n2l,  g_n2_l);
    cudaGetSymbolAddress((void**)&ffh,  g_ff_h);  cudaGetSymbolAddress((void**)&ffl,  g_ff_l);

    __nv_bfloat16 *Winh, *Winl, *Wqh, *Wql, *Wkh, *Wkl, *Wvh, *Wvl, *Woh, *Wol,
                  *W2h, *W2l, *Wf1h, *Wf1l, *Wf2h, *Wf2l;
    cudaGetSymbolAddress((void**)&Winh, g_Win_h); cudaGetSymbolAddress((void**)&Winl, g_Win_l);
    cudaGetSymbolAddress((void**)&Wqh,  g_Wq_h);  cudaGetSymbolAddress((void**)&Wql,  g_Wq_l);
    cudaGetSymbolAddress((void**)&Wkh,  g_Wk_h);  cudaGetSymbolAddress((void**)&Wkl,  g_Wk_l);
    cudaGetSymbolAddress((void**)&Wvh,  g_Wv_h);  cudaGetSymbolAddress((void**)&Wvl,  g_Wv_l);
    cudaGetSymbolAddress((void**)&Woh,  g_Wo_h);  cudaGetSymbolAddress((void**)&Wol,  g_Wo_l);
    cudaGetSymbolAddress((void**)&W2h,  g_W2_h);  cudaGetSymbolAddress((void**)&W2l,  g_W2_l);
    cudaGetSymbolAddress((void**)&Wf1h, g_Wf1_h); cudaGetSymbolAddress((void**)&Wf1l, g_Wf1_l);
    cudaGetSymbolAddress((void**)&Wf2h, g_Wf2_h); cudaGetSymbolAddress((void**)&Wf2l, g_Wf2_l);

    // 0) split weights into bf16 hi/lo
    split_kernel<<<D * D / 256, 256>>>(W_in, Winh, Winl);
    split_kernel<<<D * D / 256, 256>>>(Wq,   Wqh,  Wql);
    split_kernel<<<D * D / 256, 256>>>(Wk,   Wkh,  Wkl);
    split_kernel<<<D * D / 256, 256>>>(Wv,   Wvh,  Wvl);
    split_kernel<<<D * D / 256, 256>>>(Wo,   Woh,  Wol);
    split_kernel<<<D * D / 256, 256>>>(W2,   W2h,  W2l);
    split_kernel<<<D * DFF / 256, 256>>>(Wf1, Wf1h, Wf1l);
    split_kernel<<<DFF * D / 256, 256>>>(Wf2, Wf2h, Wf2l);

    // 1) LN1 -> split only
    ln_kernel<<<S, 256>>>(x, g1, beta1, nullptr, nxh, nxl);
    // 2) h = nx @ W_in + b_in  -> split only
    gemm_mma<<<dim3(D / 64, S / 128), 256>>>(nxh, nxl, Winh, Winl, b_in, nullptr,
                                             nullptr, hh, hl, D, D, 0);
    // 3) q/k/v -> fp32
    gemm_mma<<<dim3(D / 64, S / 128), 256>>>(hh, hl, Wqh, Wql, bq, nullptr,
                                             q, nullptr, nullptr, D, D, 0);
    gemm_mma<<<dim3(D / 64, S / 128), 256>>>(hh, hl, Wkh, Wkl, bk, nullptr,
                                             k, nullptr, nullptr, D, D, 0);
    gemm_mma<<<dim3(D / 64, S / 128), 256>>>(hh, hl, Wvh, Wvl, bv, nullptr,
                                             v, nullptr, nullptr, D, D, 0);
    // 4) causal scores into attn region of d_out
    scores_kernel<<<dim3(32, 32, H), 256>>>(q, k, attn);
    // 5) in-place causal softmax -> final attn_weights
    softmax_kernel<<<dim3(S, H), 256>>>(attn);
    // 6) ctx = attn @ v (split output)
    ctx_kernel<<<dim3(32, H), 256>>>(attn, v, ctxh, ctxl);
    // 7) mha_out = ctx @ Wo + bo -> split only
    gemm_mma<<<dim3(D / 64, S / 128), 256>>>(ctxh, ctxl, Woh, Wol, bo, nullptr,
                                             nullptr, tmph, tmpl, D, D, 0);
    // 8) part1 = x + (mha_out @ W2 + b2) -> fp32
    gemm_mma<<<dim3(D / 64, S / 128), 256>>>(tmph, tmpl, W2h, W2l, b2, x,
                                             part1, nullptr, nullptr, D, D, 0);
    // 9) LN2 -> fp32 + split
    ln_kernel<<<S, 256>>>(part1, g2, beta2, n2, n2h, n2l);
    // 10) ff = relu(n2 @ Wf1 + bf1) -> split only
    gemm_mma<<<dim3(DFF / 64, S / 128), 256>>>(n2h, n2l, Wf1h, Wf1l, bf1, nullptr,
                                               nullptr, ffh, ffl, DFF, D, 1);
    // 11) out = n2 + (ff @ Wf2 + bf2) -> fp32 (final)
    gemm_mma<<<dim3(D / 64, S / 128), 256>>>(ffh, ffl, Wf2h, Wf2l, bf2, n2,
                                             out, nullptr, nullptr, D, DFF, 0);
}

// round 6
// speedup vs baseline: 2.3012x; 1.1577x over previous
#include <cuda_runtime.h>
#include <cuda_bf16.h>
#include <math.h>
#include <stdint.h>

// ---------------------------------------------------------------------------
// TransformerBlock: S=2048, d=1024, H=16, dk=64, dff=4096, B=1
// Output = concat(out [2048*1024], attn_weights [16*2048*2048]) fp32
// All GEMMs + attention matmuls on tensor cores (mma.sync bf16) with
// split-fp32 compensation: C = Ah*Bh + Ah*Bl + Al*Bh (fp32 accum).
// ---------------------------------------------------------------------------

#define S 2048
#define D 1024
#define H 16
#define DFF 4096
#define NQKV 3072
#define OUT_ELEMS (S * D)

// fp32 scratch
__device__ float g_qkv[S * NQKV];     // [s][ q(0:1024) | k(1024:2048) | v(2048:3072) ]
__device__ float g_part1[S * D];
__device__ float g_n2[S * D];
__device__ float g_bqkv[NQKV];
// bf16 hi/lo split activations
__device__ __nv_bfloat16 g_nx_h[S * D],  g_nx_l[S * D];
__device__ __nv_bfloat16 g_h_h[S * D],   g_h_l[S * D];
__device__ __nv_bfloat16 g_ctx_h[S * D], g_ctx_l[S * D];
__device__ __nv_bfloat16 g_tmp_h[S * D], g_tmp_l[S * D];
__device__ __nv_bfloat16 g_n2_h[S * D],  g_n2_l[S * D];
__device__ __nv_bfloat16 g_ff_h[S * DFF], g_ff_l[S * DFF];
// bf16 hi/lo split weights
__device__ __nv_bfloat16 g_Win_h[D * D],    g_Win_l[D * D];
__device__ __nv_bfloat16 g_Wqkv_h[D * NQKV], g_Wqkv_l[D * NQKV];  // concat q|k|v
__device__ __nv_bfloat16 g_Wo_h[D * D],     g_Wo_l[D * D];
__device__ __nv_bfloat16 g_W2_h[D * D],     g_W2_l[D * D];
__device__ __nv_bfloat16 g_Wf1_h[D * DFF],  g_Wf1_l[D * DFF];
__device__ __nv_bfloat16 g_Wf2_h[DFF * D],  g_Wf2_l[DFF * D];

// ---------------------------------------------------------------------------
// helpers
// ---------------------------------------------------------------------------
__device__ __forceinline__ void split2(float v, __nv_bfloat16& h, __nv_bfloat16& l) {
    h = __float2bfloat16(v);
    l = __float2bfloat16(v - __bfloat162float(h));
}

__device__ __forceinline__ uint32_t smem_u32(const void* p) {
    return (uint32_t)__cvta_generic_to_shared(p);
}

__device__ __forceinline__ void cp16(void* smem, const void* g) {
    uint32_t s = smem_u32(smem);
    asm volatile("cp.async.cg.shared.global [%0], [%1], 16;\n" :: "r"(s), "l"(g));
}

__device__ __forceinline__ void ldm_x4(uint32_t* r, uint32_t addr) {
    asm volatile("ldmatrix.sync.aligned.m8n8.x4.shared.b16 {%0,%1,%2,%3}, [%4];\n"
                 : "=r"(r[0]), "=r"(r[1]), "=r"(r[2]), "=r"(r[3]) : "r"(addr));
}

__device__ __forceinline__ void ldm_x4_trans(uint32_t* r, uint32_t addr) {
    asm volatile("ldmatrix.sync.aligned.m8n8.x4.trans.shared.b16 {%0,%1,%2,%3}, [%4];\n"
                 : "=r"(r[0]), "=r"(r[1]), "=r"(r[2]), "=r"(r[3]) : "r"(addr));
}

__device__ __forceinline__ void mma16816(float* c, const uint32_t* a, const uint32_t* b) {
    asm volatile(
        "mma.sync.aligned.m16n8k16.row.col.f32.bf16.bf16.f32 "
        "{%0,%1,%2,%3}, {%4,%5,%6,%7}, {%8,%9}, {%0,%1,%2,%3};\n"
        : "+f"(c[0]), "+f"(c[1]), "+f"(c[2]), "+f"(c[3])
        : "r"(a[0]), "r"(a[1]), "r"(a[2]), "r"(a[3]), "r"(b[0]), "r"(b[1]));
}

// ---------------------------------------------------------------------------
// split8: all weight splits in one launch. Job table passed by value.
// grid = (4096, 8); 1M-element jobs use first 1024 blocks.
// ---------------------------------------------------------------------------
struct SplitJob {
    const float* src;
    __nv_bfloat16* h;
    __nv_bfloat16* l;
    int srcN;     // source row width
    int dstLd;    // dest leading dim
    int colOfs;   // dest column offset
    int nblocks;  // nelem / 1024
};
struct SplitJobs { SplitJob j[8]; };

__global__ __launch_bounds__(256) void split8_kernel(SplitJobs jobs)
{
    const SplitJob jb = jobs.j[blockIdx.y];
    if ((int)blockIdx.x >= jb.nblocks) return;
    int i0 = blockIdx.x * 1024 + threadIdx.x * 4;
    float4 v = *reinterpret_cast<const float4*>(jb.src + i0);
    int row = i0 / jb.srcN, n = i0 % jb.srcN;
    size_t d = (size_t)row * jb.dstLd + jb.colOfs + n;
    __nv_bfloat16 h0, l0, h1, l1, h2, l2, h3, l3;
    split2(v.x, h0, l0); split2(v.y, h1, l1);
    split2(v.z, h2, l2); split2(v.w, h3, l3);
    __nv_bfloat162 p;
    p.x = h0; p.y = h1; *reinterpret_cast<__nv_bfloat162*>(jb.h + d) = p;
    p.x = h2; p.y = h3; *reinterpret_cast<__nv_bfloat162*>(jb.h + d + 2) = p;
    p.x = l0; p.y = l1; *reinterpret_cast<__nv_bfloat162*>(jb.l + d) = p;
    p.x = l2; p.y = l3; *reinterpret_cast<__nv_bfloat162*>(jb.l + d + 2) = p;
}

// bias concat for qkv
__global__ void bias_concat_kernel(const float* __restrict__ bq,
                                   const float* __restrict__ bk,
                                   const float* __restrict__ bv,
                                   float* __restrict__ dst)
{
    int i = threadIdx.x;
    const float* src = blockIdx.x == 0 ? bq : (blockIdx.x == 1 ? bk : bv);
    dst[blockIdx.x * 1024 + i] = src[i];
}

// ---------------------------------------------------------------------------
// LayerNorm (biased var, (x-m)/(std+eps)); writes bf16 hi/lo, fp32 optional.
// ---------------------------------------------------------------------------
__global__ __launch_bounds__(256) void ln_kernel(
    const float* __restrict__ x, const float* __restrict__ g,
    const float* __restrict__ b, float* __restrict__ yf,
    __nv_bfloat16* __restrict__ yh, __nv_bfloat16* __restrict__ yl)
{
    const int row = blockIdx.x;
    const float* xr = x + (size_t)row * D;
    float vals[4];
    float s = 0.f, s2 = 0.f;
#pragma unroll
    for (int t = 0; t < 4; t++) {
        float u = xr[threadIdx.x + t * 256];
        vals[t] = u;
        s += u;
        s2 += u * u;
    }
    __shared__ float sm1[8], sm2[8];
#pragma unroll
    for (int o = 16; o; o >>= 1) {
        s  += __shfl_xor_sync(0xffffffffu, s,  o);
        s2 += __shfl_xor_sync(0xffffffffu, s2, o);
    }
    int wid = threadIdx.x >> 5;
    if ((threadIdx.x & 31) == 0) { sm1[wid] = s; sm2[wid] = s2; }
    __syncthreads();
    if (threadIdx.x < 8) {
        float a = sm1[threadIdx.x], c = sm2[threadIdx.x];
#pragma unroll
        for (int o = 4; o; o >>= 1) {
            a += __shfl_xor_sync(0xffu, a, o);
            c += __shfl_xor_sync(0xffu, c, o);
        }
        if (threadIdx.x == 0) { sm1[0] = a; sm2[0] = c; }
    }
    __syncthreads();
    float mean = sm1[0] * (1.f / D);
    float var = fmaxf(sm2[0] * (1.f / D) - mean * mean, 0.f);
    float inv = 1.f / (sqrtf(var) + 1e-6f);
#pragma unroll
    for (int t = 0; t < 4; t++) {
        int c = threadIdx.x + t * 256;
        float v = g[c] * ((vals[t] - mean) * inv) + b[c];
        size_t idx = (size_t)row * D + c;
        if (yf) yf[idx] = v;
        __nv_bfloat16 hi, lo;
        split2(v, hi, lo);
        yh[idx] = hi;
        yl[idx] = lo;
    }
}

// ---------------------------------------------------------------------------
// Tensor-core GEMM (unchanged from R4): BM=128, BN=64, BK=16, 2-stage cp.async.
// ---------------------------------------------------------------------------
__global__ __launch_bounds__(256) void gemm_mma(
    const __nv_bfloat16* __restrict__ Ah, const __nv_bfloat16* __restrict__ Al,
    const __nv_bfloat16* __restrict__ Bh, const __nv_bfloat16* __restrict__ Bl,
    const float* __restrict__ bias, const float* __restrict__ res,
    float* __restrict__ Cf, __nv_bfloat16* __restrict__ Ch,
    __nv_bfloat16* __restrict__ Cl, int N, int K, int relu)
{
    __shared__ __align__(16) __nv_bfloat16 As[2][2][128][24];
    __shared__ __align__(16) __nv_bfloat16 Bs[2][2][16][72];

    const int tid = threadIdx.x;
    const int m0 = blockIdx.y * 128, n0 = blockIdx.x * 64;
    const int warp = tid >> 5, lane = tid & 31;
    const int wm = warp >> 1, wn = warp & 1;

    float acc[2][4][4] = {};

    auto issue = [&](int stg, int it) {
        const int k0 = it * 16;
        const int ar = tid >> 1, ac = (tid & 1) * 8;
        cp16(&As[stg][0][ar][ac], Ah + (size_t)(m0 + ar) * K + k0 + ac);
        cp16(&As[stg][1][ar][ac], Al + (size_t)(m0 + ar) * K + k0 + ac);
        if (tid < 128) {
            const int br = tid >> 3, bc = (tid & 7) * 8;
            cp16(&Bs[stg][0][br][bc], Bh + (size_t)(k0 + br) * N + n0 + bc);
        } else {
            const int t2 = tid - 128, br = t2 >> 3, bc = (t2 & 7) * 8;
            cp16(&Bs[stg][1][br][bc], Bl + (size_t)(k0 + br) * N + n0 + bc);
        }
        asm volatile("cp.async.commit_group;\n" ::: "memory");
    };

    const int nIter = K >> 4;
    issue(0, 0);
    for (int it = 0; it < nIter; ++it) {
        const int s = it & 1;
        if (it + 1 < nIter) {
            issue(s ^ 1, it + 1);
            asm volatile("cp.async.wait_group 1;\n" ::: "memory");
        } else {
            asm volatile("cp.async.wait_group 0;\n" ::: "memory");
        }
        __syncthreads();

        uint32_t a[2][2][4];
        uint32_t b[2][4][2];
#pragma unroll
        for (int hl = 0; hl < 2; hl++) {
#pragma unroll
            for (int mt = 0; mt < 2; mt++) {
                uint32_t addr = smem_u32(
                    &As[s][hl][wm * 32 + mt * 16 + (lane & 15)][(lane >> 4) * 8]);
                ldm_x4(a[hl][mt], addr);
            }
#pragma unroll
            for (int np = 0; np < 2; np++) {
                uint32_t r4[4];
                uint32_t addr = smem_u32(
                    &Bs[s][hl][lane & 15][wn * 32 + np * 16 + (lane >> 4) * 8]);
                ldm_x4_trans(r4, addr);
                b[hl][np * 2][0]     = r4[0];
                b[hl][np * 2][1]     = r4[1];
                b[hl][np * 2 + 1][0] = r4[2];
                b[hl][np * 2 + 1][1] = r4[3];
            }
        }
#pragma unroll
        for (int mt = 0; mt < 2; mt++)
#pragma unroll
            for (int nt = 0; nt < 4; nt++) {
                mma16816(acc[mt][nt], a[0][mt], b[0][nt]);
                mma16816(acc[mt][nt], a[0][mt], b[1][nt]);
                mma16816(acc[mt][nt], a[1][mt], b[0][nt]);
            }
        __syncthreads();
    }

#pragma unroll
    for (int mt = 0; mt < 2; mt++) {
#pragma unroll
        for (int nt = 0; nt < 4; nt++) {
            int r = m0 + wm * 32 + mt * 16 + (lane >> 2);
            int c = n0 + wn * 32 + nt * 8 + (lane & 3) * 2;
            float b0 = bias[c], b1 = bias[c + 1];
            float v0 = acc[mt][nt][0] + b0;
            float v1 = acc[mt][nt][1] + b1;
            float v2 = acc[mt][nt][2] + b0;
            float v3 = acc[mt][nt][3] + b1;
            if (relu) {
                v0 = fmaxf(v0, 0.f); v1 = fmaxf(v1, 0.f);
                v2 = fmaxf(v2, 0.f); v3 = fmaxf(v3, 0.f);
            }
            if (res) {
                v0 += res[(size_t)r * N + c];
                v1 += res[(size_t)r * N + c + 1];
                v2 += res[(size_t)(r + 8) * N + c];
                v3 += res[(size_t)(r + 8) * N + c + 1];
            }
            if (Cf) {
                *(float2*)&Cf[(size_t)r * N + c] = make_float2(v0, v1);
                *(float2*)&Cf[(size_t)(r + 8) * N + c] = make_float2(v2, v3);
            }
            if (Ch) {
                __nv_bfloat16 h0, l0, h1, l1, h2, l2, h3, l3;
                split2(v0, h0, l0); split2(v1, h1, l1);
                split2(v2, h2, l2); split2(v3, h3, l3);
                __nv_bfloat162 hv, lv;
                hv.x = h0; hv.y = h1; lv.x = l0; lv.y = l1;
                *(__nv_bfloat162*)&Ch[(size_t)r * N + c] = hv;
                *(__nv_bfloat162*)&Cl[(size_t)r * N + c] = lv;
                hv.x = h2; hv.y = h3; lv.x = l2; lv.y = l3;
                *(__nv_bfloat162*)&Ch[(size_t)(r + 8) * N + c] = hv;
                *(__nv_bfloat162*)&Cl[(size_t)(r + 8) * N + c] = lv;
            }
        }
    }
}

// ---------------------------------------------------------------------------
// scores_mma: attn_raw = (Q K^T)/8 for lower-tri 64x64 tiles, bf16 split MMA.
// Q/K loaded fp32 from qkv buffer, split in-kernel. 256 thr, 8 warps (4x2).
// ---------------------------------------------------------------------------
__global__ __launch_bounds__(256) void scores_mma(
    const float* __restrict__ qkv, float* __restrict__ attn)
{
    const int kt = blockIdx.x, qt = blockIdx.y, h = blockIdx.z;
    if (kt > qt) return;
    __shared__ __align__(16) __nv_bfloat16 Qh[64][72], Ql[64][72];
    __shared__ __align__(16) __nv_bfloat16 Kh[64][72], Kl[64][72];
    const int tid = threadIdx.x;
    for (int i = tid; i < 64 * 64; i += 256) {
        int r = i >> 6, c = i & 63;
        float qv = qkv[(size_t)(qt * 64 + r) * NQKV + h * 64 + c];
        float kv = qkv[(size_t)(kt * 64 + r) * NQKV + 1024 + h * 64 + c];
        split2(qv, Qh[r][c], Ql[r][c]);
        split2(kv, Kh[r][c], Kl[r][c]);
    }
    __syncthreads();

    const int warp = tid >> 5, lane = tid & 31;
    const int wr = (warp >> 1) * 16, wc = (warp & 1) * 32;
    float acc[4][4] = {};

#pragma unroll
    for (int k0 = 0; k0 < 64; k0 += 16) {
        uint32_t a[2][4];
        ldm_x4(a[0], smem_u32(&Qh[wr + (lane & 15)][k0 + (lane >> 4) * 8]));
        ldm_x4(a[1], smem_u32(&Ql[wr + (lane & 15)][k0 + (lane >> 4) * 8]));
        uint32_t b[2][4][2];
        const int grp = lane >> 3, rr = lane & 7;
        const int nrow = ((grp >> 1) * 8) + rr, kofs = k0 + (grp & 1) * 8;
#pragma unroll
        for (int np = 0; np < 2; np++) {
            uint32_t r4[4];
            ldm_x4(r4, smem_u32(&Kh[wc + np * 16 + nrow][kofs]));
            b[0][np * 2][0] = r4[0]; b[0][np * 2][1] = r4[1];
            b[0][np * 2 + 1][0] = r4[2]; b[0][np * 2 + 1][1] = r4[3];
            ldm_x4(r4, smem_u32(&Kl[wc + np * 16 + nrow][kofs]));
            b[1][np * 2][0] = r4[0]; b[1][np * 2][1] = r4[1];
            b[1][np * 2 + 1][0] = r4[2]; b[1][np * 2 + 1][1] = r4[3];
        }
#pragma unroll
        for (int nt = 0; nt < 4; nt++) {
            mma16816(acc[nt], a[0], b[0][nt]);
            mma16816(acc[nt], a[0], b[1][nt]);
            mma16816(acc[nt], a[1], b[0][nt]);
        }
    }

    float* out = attn + ((size_t)(h * S + qt * 64)) * S + kt * 64;
#pragma unroll
    for (int nt = 0; nt < 4; nt++) {
        int r = wr + (lane >> 2);
        int c = wc + nt * 8 + (lane & 3) * 2;
        out[(size_t)r * S + c]       = acc[nt][0] * 0.125f;
        out[(size_t)r * S + c + 1]   = acc[nt][1] * 0.125f;
        out[(size_t)(r + 8) * S + c]     = acc[nt][2] * 0.125f;
        out[(size_t)(r + 8) * S + c + 1] = acc[nt][3] * 0.125f;
    }
}

// ---------------------------------------------------------------------------
// Causal softmax in-place. grid: (row=2048, head=16).
// ---------------------------------------------------------------------------
__global__ __launch_bounds__(256) void softmax_kernel(float* __restrict__ attn)
{
    const int i = blockIdx.x, h = blockIdx.y;
    float* row = attn + ((size_t)h * S + i) * S;
    const int len = i + 1;
    const int tid = threadIdx.x;
    float v[8];
    float mx = -INFINITY;
#pragma unroll
    for (int t = 0; t < 8; t++) {
        int j = tid + t * 256;
        v[t] = (j < len) ? row[j] : -INFINITY;
        mx = fmaxf(mx, v[t]);
    }
    __shared__ float sm[8];
#pragma unroll
    for (int o = 16; o; o >>= 1) mx = fmaxf(mx, __shfl_xor_sync(0xffffffffu, mx, o));
    int wid = tid >> 5;
    if ((tid & 31) == 0) sm[wid] = mx;
    __syncthreads();
    if (tid < 8) {
        float w = sm[tid];
#pragma unroll
        for (int o = 4; o; o >>= 1) w = fmaxf(w, __shfl_xor_sync(0xffu, w, o));
        if (tid == 0) sm[0] = w;
    }
    __syncthreads();
    const float rmax = sm[0];
    __syncthreads();

    float sum = 0.f;
#pragma unroll
    for (int t = 0; t < 8; t++) {
        int j = tid + t * 256;
        float e = (j < len) ? __expf(v[t] - rmax) : 0.f;
        v[t] = e;
        sum += e;
    }
#pragma unroll
    for (int o = 16; o; o >>= 1) sum += __shfl_xor_sync(0xffffffffu, sum, o);
    if ((tid & 31) == 0) sm[wid] = sum;
    __syncthreads();
    if (tid < 8) {
        float w = sm[tid];
#pragma unroll
        for (int o = 4; o; o >>= 1) w += __shfl_xor_sync(0xffu, w, o);
        if (tid == 0) sm[0] = w;
    }
    __syncthreads();
    const float inv = 1.f / sm[0];
#pragma unroll
    for (int t = 0; t < 8; t++) {
        int j = tid + t * 256;
        row[j] = v[t] * inv;
    }
}

// ---------------------------------------------------------------------------
// ctx_mma: ctx = attn @ V per head (skip kt>qt), bf16 split MMA, in-kernel
// fp32->split conversion. 256 thr, 8 warps (4x2). Output: bf16 hi/lo.
// ---------------------------------------------------------------------------
__global__ __launch_bounds__(256) void ctx_mma(
    const float* __restrict__ attn, const float* __restrict__ qkv,
    __nv_bfloat16* __restrict__ ch, __nv_bfloat16* __restrict__ cl)
{
    const int qt = blockIdx.x, h = blockIdx.y;
    __shared__ __align__(16) __nv_bfloat16 Ah[64][72], Al[64][72];
    __shared__ __align__(16) __nv_bfloat16 Vh[64][72], Vl[64][72];
    const int tid = threadIdx.x;
    const int warp = tid >> 5, lane = tid & 31;
    const int wr = (warp >> 1) * 16, wc = (warp & 1) * 32;
    float acc[4][4] = {};

    for (int kt = 0; kt <= qt; kt++) {
        for (int i = tid; i < 64 * 64; i += 256) {
            int r = i >> 6, c = i & 63;
            float av = attn[((size_t)(h * S + qt * 64 + r)) * S + kt * 64 + c];
            float vv = qkv[(size_t)(kt * 64 + r) * NQKV + 2048 + h * 64 + c];
            split2(av, Ah[r][c], Al[r][c]);
            split2(vv, Vh[r][c], Vl[r][c]);
        }
        __syncthreads();
#pragma unroll
        for (int k0 = 0; k0 < 64; k0 += 16) {
            uint32_t a[2][4];
            ldm_x4(a[0], smem_u32(&Ah[wr + (lane & 15)][k0 + (lane >> 4) * 8]));
            ldm_x4(a[1], smem_u32(&Al[wr + (lane & 15)][k0 + (lane >> 4) * 8]));
            uint32_t b[2][4][2];
#pragma unroll
            for (int np = 0; np < 2; np++) {
                uint32_t r4[4];
                ldm_x4_trans(r4, smem_u32(&Vh[k0 + (lane & 15)][wc + np * 16 + (lane >> 4) * 8]));
                b[0][np * 2][0] = r4[0]; b[0][np * 2][1] = r4[1];
                b[0][np * 2 + 1][0] = r4[2]; b[0][np * 2 + 1][1] = r4[3];
                ldm_x4_trans(r4, smem_u32(&Vl[k0 + (lane & 15)][wc + np * 16 + (lane >> 4) * 8]));
                b[1][np * 2][0] = r4[0]; b[1][np * 2][1] = r4[1];
                b[1][np * 2 + 1][0] = r4[2]; b[1][np * 2 + 1][1] = r4[3];
            }
#pragma unroll
            for (int nt = 0; nt < 4; nt++) {
                mma16816(acc[nt], a[0], b[0][nt]);
                mma16816(acc[nt], a[0], b[1][nt]);
                mma16816(acc[nt], a[1], b[0][nt]);
            }
        }
        __syncthreads();
    }

#pragma unroll
    for (int nt = 0; nt < 4; nt++) {
        int r = qt * 64 + wr + (lane >> 2);
        int c = h * 64 + wc + nt * 8 + (lane & 3) * 2;
        __nv_bfloat16 h0, l0, h1, l1;
        split2(acc[nt][0], h0, l0); split2(acc[nt][1], h1, l1);
        __nv_bfloat162 hv, lv;
        hv.x = h0; hv.y = h1; lv.x = l0; lv.y = l1;
        *(__nv_bfloat162*)&ch[(size_t)r * D + c] = hv;
        *(__nv_bfloat162*)&cl[(size_t)r * D + c] = lv;
        split2(acc[nt][2], h0, l0); split2(acc[nt][3], h1, l1);
        hv.x = h0; hv.y = h1; lv.x = l0; lv.y = l1;
        *(__nv_bfloat162*)&ch[(size_t)(r + 8) * D + c] = hv;
        *(__nv_bfloat162*)&cl[(size_t)(r + 8) * D + c] = lv;
    }
}

// ---------------------------------------------------------------------------
// Host launcher
// ---------------------------------------------------------------------------
extern "C" void kernel_launch(void* const* d_in, const int* in_sizes, int n_in,
                              void* d_out, int out_size)
{
    (void)in_sizes; (void)n_in; (void)out_size;
    const float* x     = (const float*)d_in[0];
    const float* g1    = (const float*)d_in[1];
    const float* beta1 = (const float*)d_in[2];
    const float* W_in  = (const float*)d_in[3];
    const float* b_in  = (const float*)d_in[4];
    const float* Wq    = (const float*)d_in[5];
    const float* bq    = (const float*)d_in[6];
    const float* Wk    = (const float*)d_in[7];
    const float* bk    = (const float*)d_in[8];
    const float* Wv    = (const float*)d_in[9];
    const float* bv    = (const float*)d_in[10];
    const float* Wo    = (const float*)d_in[11];
    const float* bo    = (const float*)d_in[12];
    const float* W2    = (const float*)d_in[13];
    const float* b2    = (const float*)d_in[14];
    const float* g2    = (const float*)d_in[15];
    const float* beta2 = (const float*)d_in[16];
    const float* Wf1   = (const float*)d_in[17];
    const float* bf1   = (const float*)d_in[18];
    const float* Wf2   = (const float*)d_in[19];
    const float* bf2   = (const float*)d_in[20];

    float* out  = (float*)d_out;
    float* attn = out + (size_t)OUT_ELEMS;   // [16,2048,2048]

    float *qkv, *part1, *n2, *bqkv;
    cudaGetSymbolAddress((void**)&qkv,   g_qkv);
    cudaGetSymbolAddress((void**)&part1, g_part1);
    cudaGetSymbolAddress((void**)&n2,    g_n2);
    cudaGetSymbolAddress((void**)&bqkv,  g_bqkv);

    __nv_bfloat16 *nxh, *nxl, *hh, *hl, *ctxh, *ctxl, *tmph, *tmpl, *n2h, *n2l, *ffh, *ffl;
    cudaGetSymbolAddress((void**)&nxh,  g_nx_h);  cudaGetSymbolAddress((void**)&nxl,  g_nx_l);
    cudaGetSymbolAddress((void**)&hh,   g_h_h);   cudaGetSymbolAddress((void**)&hl,   g_h_l);
    cudaGetSymbolAddress((void**)&ctxh, g_ctx_h); cudaGetSymbolAddress((void**)&ctxl, g_ctx_l);
    cudaGetSymbolAddress((void**)&tmph, g_tmp_h); cudaGetSymbolAddress((void**)&tmpl, g_tmp_l);
    cudaGetSymbolAddress((void**)&n2h,  g_n2_h);  cudaGetSymbolAddress((void**)&n2l,  g_n2_l);
    cudaGetSymbolAddress((void**)&ffh,  g_ff_h);  cudaGetSymbolAddress((void**)&ffl,  g_ff_l);

    __nv_bfloat16 *Winh, *Winl, *Wqkvh, *Wqkvl, *Woh, *Wol, *W2h, *W2l,
                  *Wf1h, *Wf1l, *Wf2h, *Wf2l;
    cudaGetSymbolAddress((void**)&Winh,  g_Win_h);  cudaGetSymbolAddress((void**)&Winl,  g_Win_l);
    cudaGetSymbolAddress((void**)&Wqkvh, g_Wqkv_h); cudaGetSymbolAddress((void**)&Wqkvl, g_Wqkv_l);
    cudaGetSymbolAddress((void**)&Woh,   g_Wo_h);   cudaGetSymbolAddress((void**)&Wol,   g_Wo_l);
    cudaGetSymbolAddress((void**)&W2h,   g_W2_h);   cudaGetSymbolAddress((void**)&W2l,   g_W2_l);
    cudaGetSymbolAddress((void**)&Wf1h,  g_Wf1_h);  cudaGetSymbolAddress((void**)&Wf1l,  g_Wf1_l);
    cudaGetSymbolAddress((void**)&Wf2h,  g_Wf2_h);  cudaGetSymbolAddress((void**)&Wf2l,  g_Wf2_l);

    // 0) all weight splits in one launch (Wq/Wk/Wv -> concatenated [1024,3072])
    SplitJobs jobs;
    jobs.j[0] = { W_in, Winh,  Winl,  D,   D,    0,    D * D / 1024 };
    jobs.j[1] = { Wq,   Wqkvh, Wqkvl, D,   NQKV, 0,    D * D / 1024 };
    jobs.j[2] = { Wk,   Wqkvh, Wqkvl, D,   NQKV, 1024, D * D / 1024 };
    jobs.j[3] = { Wv,   Wqkvh, Wqkvl, D,   NQKV, 2048, D * D / 1024 };
    jobs.j[4] = { Wo,   Woh,   Wol,   D,   D,    0,    D * D / 1024 };
    jobs.j[5] = { W2,   W2h,   W2l,   D,   D,    0,    D * D / 1024 };
    jobs.j[6] = { Wf1,  Wf1h,  Wf1l,  DFF, DFF,  0,    D * DFF / 1024 };
    jobs.j[7] = { Wf2,  Wf2h,  Wf2l,  D,   D,    0,    DFF * D / 1024 };
    split8_kernel<<<dim3(D * DFF / 1024, 8), 256>>>(jobs);
    bias_concat_kernel<<<3, 1024>>>(bq, bk, bv, bqkv);

    // 1) LN1 -> split
    ln_kernel<<<S, 256>>>(x, g1, beta1, nullptr, nxh, nxl);
    // 2) h = nx @ W_in + b_in -> split
    gemm_mma<<<dim3(D / 64, S / 128), 256>>>(nxh, nxl, Winh, Winl, b_in, nullptr,
                                             nullptr, hh, hl, D, D, 0);
    // 3) qkv = h @ [Wq|Wk|Wv] + [bq|bk|bv] -> fp32 [2048,3072]
    gemm_mma<<<dim3(NQKV / 64, S / 128), 256>>>(hh, hl, Wqkvh, Wqkvl, bqkv, nullptr,
                                                qkv, nullptr, nullptr, NQKV, D, 0);
    // 4) causal scores into attn region (tensor cores)
    scores_mma<<<dim3(32, 32, H), 256>>>(qkv, attn);
    // 5) in-place causal softmax -> final attn_weights
    softmax_kernel<<<dim3(S, H), 256>>>(attn);
    // 6) ctx = attn @ v (tensor cores, split output)
    ctx_mma<<<dim3(32, H), 256>>>(attn, qkv, ctxh, ctxl);
    // 7) mha_out = ctx @ Wo + bo -> split
    gemm_mma<<<dim3(D / 64, S / 128), 256>>>(ctxh, ctxl, Woh, Wol, bo, nullptr,
                                             nullptr, tmph, tmpl, D, D, 0);
    // 8) part1 = x + (mha_out @ W2 + b2) -> fp32
    gemm_mma<<<dim3(D / 64, S / 128), 256>>>(tmph, tmpl, W2h, W2l, b2, x,
                                             part1, nullptr, nullptr, D, D, 0);
    // 9) LN2 -> fp32 + split
    ln_kernel<<<S, 256>>>(part1, g2, beta2, n2, n2h, n2l);
    // 10) ff = relu(n2 @ Wf1 + bf1) -> split
    gemm_mma<<<dim3(DFF / 64, S / 128), 256>>>(n2h, n2l, Wf1h, Wf1l, bf1, nullptr,
                                               nullptr, ffh, ffl, DFF, D, 1);
    // 11) out = n2 + (ff @ Wf2 + bf2) -> fp32 (final)
    gemm_mma<<<dim3(D / 64, S / 128), 256>>>(ffh, ffl, Wf2h, Wf2l, bf2, n2,
                                             out, nullptr, nullptr, D, DFF, 0);
}